// round 4
// baseline (speedup 1.0000x reference)
#include <cuda_runtime.h>
#include <math.h>

#define TFv  8192
#define TF2v 4096
#define TPv  512
#define Bv   16
#define EPSv 1e-8f

// Scratch (no allocations allowed -> device globals)
__device__ float g_d2pair[Bv * TF2v];
__device__ float g_f0pair[Bv * TF2v];
__device__ float g_e[Bv];

// ---------------------------------------------------------------------------
// Kernel 1: per-batch frame pipeline: interp unvoiced -> SG smooth -> |d2|,
// then pair-fold to TF2 resolution (nearest upsample means frame t uses attn
// column t/2, so we only ever need d2[2j]+d2[2j+1] and f0[2j]+f0[2j+1]).
// One block per batch, everything in shared memory.
// ---------------------------------------------------------------------------
__global__ void __launch_bounds__(512) frame_kernel(const float* __restrict__ f0g) {
    extern __shared__ char smem_raw[];
    float* s_f0  = (float*)smem_raw;            // original f0
    float* s_a   = s_f0  + TFv;                 // interpolated
    float* s_b   = s_a   + TFv;                 // smoothed
    int*   s_prev = (int*)(s_b + TFv);          // last voiced idx <= t
    int*   s_next = s_prev + TFv;               // first voiced idx >= t
    __shared__ int s_part[512];

    const int b    = blockIdx.x;
    const int tid  = threadIdx.x;
    const int nthr = 512;
    const int chunk = TFv / nthr;               // 16
    const float* f0 = f0g + (size_t)b * TFv;

    for (int t = tid; t < TFv; t += nthr) s_f0[t] = f0[t];
    __syncthreads();

    const int base = tid * chunk;

    // forward cummax of (voiced ? t : -1)
    {
        int run = -1;
        #pragma unroll
        for (int i = 0; i < chunk; ++i) {
            int t = base + i;
            if (s_f0[t] > 0.0f) run = t;
            s_prev[t] = run;
        }
        s_part[tid] = run;
    }
    __syncthreads();
    if (tid == 0) {
        int acc = -1;
        for (int i = 0; i < nthr; ++i) { int v = s_part[i]; s_part[i] = acc; if (v > acc) acc = v; }
    }
    __syncthreads();
    {
        int pre = s_part[tid];
        #pragma unroll
        for (int i = 0; i < chunk; ++i) {
            int t = base + i;
            if (s_prev[t] < pre) s_prev[t] = pre;
        }
    }
    __syncthreads();

    // backward cummin of (voiced ? t : TF)
    {
        int run = TFv;
        #pragma unroll
        for (int i = chunk - 1; i >= 0; --i) {
            int t = base + i;
            if (s_f0[t] > 0.0f) run = t;
            s_next[t] = run;
        }
        s_part[tid] = run;
    }
    __syncthreads();
    if (tid == 0) {
        int acc = TFv;
        for (int i = nthr - 1; i >= 0; --i) { int v = s_part[i]; s_part[i] = acc; if (v < acc) acc = v; }
    }
    __syncthreads();
    {
        int suf = s_part[tid];
        #pragma unroll
        for (int i = 0; i < chunk; ++i) {
            int t = base + i;
            if (s_next[t] > suf) s_next[t] = suf;
        }
    }
    __syncthreads();

    // linear interpolation of unvoiced frames (with edge clamping)
    for (int t = tid; t < TFv; t += nthr) {
        float f = s_f0[t];
        if (f > 0.0f) {
            s_a[t] = f;
        } else {
            int lo = s_prev[t], hi = s_next[t];
            int lo_t = (lo >= 0)  ? lo : hi;
            int hi_t = (hi < TFv) ? hi : lo;
            float lov = s_f0[lo_t];
            float hiv = s_f0[hi_t];
            int sp = hi_t - lo_t; if (sp < 1) sp = 1;
            float w = ((float)t - (float)lo_t) / (float)sp;
            w = fminf(fmaxf(w, 0.0f), 1.0f);
            s_a[t] = lov + w * (hiv - lov);
        }
    }
    __syncthreads();

    // Savitzky-Golay smooth (window 7, order 2), replicate padding
    {
        const float c0 = -2.0f / 21.0f, c1 = 3.0f / 21.0f, c2 = 6.0f / 21.0f, c3 = 7.0f / 21.0f;
        for (int t = tid; t < TFv; t += nthr) {
            int m1 = t-1 > 0 ? t-1 : 0;
            int m2 = t-2 > 0 ? t-2 : 0;
            int m3 = t-3 > 0 ? t-3 : 0;
            int p1 = t+1 < TFv-1 ? t+1 : TFv-1;
            int p2 = t+2 < TFv-1 ? t+2 : TFv-1;
            int p3 = t+3 < TFv-1 ? t+3 : TFv-1;
            float acc = c3 * s_a[t]
                      + c2 * (s_a[m1] + s_a[p1])
                      + c1 * (s_a[m2] + s_a[p2])
                      + c0 * (s_a[m3] + s_a[p3]);
            s_b[t] = acc;
        }
    }
    __syncthreads();

    // |second derivative| (replicate pad) and pair-fold to TF2, plus f0 pairs
    for (int j = tid; j < TF2v; j += nthr) {
        int t0 = 2 * j, t1 = 2 * j + 1;
        int t0m = t0 - 1 > 0 ? t0 - 1 : 0;
        int t1p = t1 + 1 < TFv - 1 ? t1 + 1 : TFv - 1;
        float d0 = fabsf(s_b[t0m] - 2.0f * s_b[t0] + s_b[t1]);
        float d1 = fabsf(s_b[t0]  - 2.0f * s_b[t1] + s_b[t1p]);
        g_d2pair[b * TF2v + j] = d0 + d1;
        g_f0pair[b * TF2v + j] = s_f0[t0] + s_f0[t1];
    }
}

// ---------------------------------------------------------------------------
// Kernel 2: the heavy one. For each (b,p) row of attn (4096 floats), fused
// triple dot: sum(attn), sum(attn*d2pair), sum(attn*f0pair). One block per row.
// 128 MB streamed once -> HBM bound (~20us floor).
// ---------------------------------------------------------------------------
__global__ void __launch_bounds__(256) row_kernel(const float* __restrict__ attn,
                                                  float* __restrict__ out) {
    const int bid = blockIdx.x;            // b*TPv + p
    const int b   = bid >> 9;
    const float4* __restrict__ row = (const float4*)attn + (size_t)bid * (TF2v / 4);
    const float4* __restrict__ d2p = (const float4*)g_d2pair + (size_t)b * (TF2v / 4);
    const float4* __restrict__ f0p = (const float4*)g_f0pair + (size_t)b * (TF2v / 4);

    float sa = 0.0f, sc = 0.0f, sm = 0.0f;
    #pragma unroll 4
    for (int i = threadIdx.x; i < TF2v / 4; i += 256) {
        float4 a = row[i];
        float4 d = d2p[i];
        float4 f = f0p[i];
        sa += (a.x + a.y) + (a.z + a.w);
        sc += a.x * d.x + a.y * d.y + a.z * d.z + a.w * d.w;
        sm += a.x * f.x + a.y * f.y + a.z * f.z + a.w * f.w;
    }
    #pragma unroll
    for (int o = 16; o > 0; o >>= 1) {
        sa += __shfl_down_sync(0xffffffffu, sa, o);
        sc += __shfl_down_sync(0xffffffffu, sc, o);
        sm += __shfl_down_sync(0xffffffffu, sm, o);
    }
    __shared__ float red[3][8];
    int w = threadIdx.x >> 5, l = threadIdx.x & 31;
    if (l == 0) { red[0][w] = sa; red[1][w] = sc; red[2][w] = sm; }
    __syncthreads();
    if (threadIdx.x == 0) {
        sa = 0.0f; sc = 0.0f; sm = 0.0f;
        #pragma unroll
        for (int i = 0; i < 8; ++i) { sa += red[0][i]; sc += red[1][i]; sm += red[2][i]; }
        float denom = fmaxf(2.0f * sa, 1.0f);
        float inv   = 1.0f / (denom + EPSv);
        out[bid]             = sc * inv;   // curv_phn
        out[Bv * TPv + bid]  = sm * inv;   // mean_phn
    }
}

// ---------------------------------------------------------------------------
// Kernel 3: per-batch masked semitone-deficit energy (both metrics fused)
// ---------------------------------------------------------------------------
__global__ void __launch_bounds__(512) energy_kernel(const float* __restrict__ uv,
                                                     const float* __restrict__ out) {
    const int b = blockIdx.x;
    const int p = threadIdx.x;
    const float OODM =  21.688259064691245f;   // 12*log2(350/100)
    const float OODC = -71.589411415945055f;   // 12*log2(1.6/100)

    float u  = uv[b * TPv + p];
    float cv = out[b * TPv + p];
    float mv = out[Bv * TPv + b * TPv + p];

    float pvm = mv * u;
    float vm  = (pvm != 0.0f) ? 1.0f : 0.0f;
    float semim = 12.0f * log2f(fmaxf(pvm, 1e-6f) * 0.01f);
    float dm  = fmaxf(OODM - semim, 0.0f) * vm;

    float pvc = cv * u;
    float vc  = (pvc != 0.0f) ? 1.0f : 0.0f;
    float semic = 12.0f * log2f(fmaxf(pvc, 1e-6f) * 0.01f);
    float dc  = fmaxf(OODC - semic, 0.0f) * vc;

    // block reduce 4 values
    #pragma unroll
    for (int o = 16; o > 0; o >>= 1) {
        dm += __shfl_down_sync(0xffffffffu, dm, o);
        vm += __shfl_down_sync(0xffffffffu, vm, o);
        dc += __shfl_down_sync(0xffffffffu, dc, o);
        vc += __shfl_down_sync(0xffffffffu, vc, o);
    }
    __shared__ float red[4][16];
    int w = threadIdx.x >> 5, l = threadIdx.x & 31;
    if (l == 0) { red[0][w] = dm; red[1][w] = vm; red[2][w] = dc; red[3][w] = vc; }
    __syncthreads();
    if (threadIdx.x == 0) {
        float Dm = 0, Vm = 0, Dc = 0, Vc = 0;
        #pragma unroll
        for (int i = 0; i < 16; ++i) { Dm += red[0][i]; Vm += red[1][i]; Dc += red[2][i]; Vc += red[3][i]; }
        g_e[b] = Dm / fmaxf(Vm, 1.0f) + Dc / fmaxf(Vc, 1.0f);
    }
}

// ---------------------------------------------------------------------------
// Kernel 4: z-score over the 16 energies, softmax(-z), B*wts, ESS
// ---------------------------------------------------------------------------
__global__ void finalize_kernel(float* __restrict__ out) {
    if (threadIdx.x != 0 || blockIdx.x != 0) return;
    float e[Bv];
    float m = 0.0f;
    #pragma unroll
    for (int i = 0; i < Bv; ++i) { e[i] = g_e[i]; m += e[i]; }
    m /= (float)Bv;
    float var = 0.0f;
    #pragma unroll
    for (int i = 0; i < Bv; ++i) { float d = e[i] - m; var += d * d; }
    var /= (float)Bv;
    float sd = fmaxf(sqrtf(var), 1e-6f);
    float x[Bv], mx = -1e30f;
    #pragma unroll
    for (int i = 0; i < Bv; ++i) { x[i] = -(e[i] - m) / sd; mx = fmaxf(mx, x[i]); }
    float s = 0.0f;
    #pragma unroll
    for (int i = 0; i < Bv; ++i) { x[i] = expf(x[i] - mx); s += x[i]; }
    float s2 = 0.0f;
    #pragma unroll
    for (int i = 0; i < Bv; ++i) { float wv = x[i] / s; x[i] = wv; s2 += wv * wv; }
    #pragma unroll
    for (int i = 0; i < Bv; ++i) out[2 * Bv * TPv + i] = (float)Bv * x[i];
    out[2 * Bv * TPv + Bv] = 1.0f / s2;
}

// ---------------------------------------------------------------------------

extern "C" void kernel_launch(void* const* d_in, const int* in_sizes, int n_in,
                              void* d_out, int out_size) {
    const float* f0   = (const float*)d_in[0];   // [B, TF]
    const float* attn = (const float*)d_in[1];   // [B, TP, TF2]
    const float* uv   = (const float*)d_in[2];   // [B, TP]
    float* out = (float*)d_out;                  // curv | mean | B*wts | ess

    const size_t smem = (size_t)5 * TFv * sizeof(float); // 160 KB
    cudaFuncSetAttribute(frame_kernel, cudaFuncAttributeMaxDynamicSharedMemorySize, (int)smem);

    frame_kernel<<<Bv, 512, smem>>>(f0);
    row_kernel<<<Bv * TPv, 256>>>(attn, out);
    energy_kernel<<<Bv, 512>>>(uv, out);
    finalize_kernel<<<1, 32>>>(out);
}

// round 6
// speedup vs baseline: 1.0762x; 1.0762x over previous
#include <cuda_runtime.h>
#include <math.h>

#define TFv  8192
#define TF2v 4096
#define TPv  512
#define Bv   16
#define EPSv 1e-8f

// Scratch (no allocations allowed -> device globals)
__device__ float g_d2pair[Bv * TF2v];
__device__ float g_f0pair[Bv * TF2v];

// ---------------------------------------------------------------------------
// Kernel 1: per-batch frame pipeline: interp unvoiced -> SG smooth -> |d2|,
// then pair-fold to TF2 resolution. One block per batch, all in shared mem.
// Block-wide partial scans are now parallel (Hillis-Steele over 512 partials).
// ---------------------------------------------------------------------------
__global__ void __launch_bounds__(512) frame_kernel(const float* __restrict__ f0g) {
    extern __shared__ char smem_raw[];
    float* s_f0  = (float*)smem_raw;            // original f0
    float* s_a   = s_f0  + TFv;                 // interpolated
    float* s_b   = s_a   + TFv;                 // smoothed
    int*   s_prev = (int*)(s_b + TFv);          // last voiced idx <= t
    int*   s_next = s_prev + TFv;               // first voiced idx >= t
    __shared__ int s_part[512];

    const int b    = blockIdx.x;
    const int tid  = threadIdx.x;
    const int nthr = 512;
    const int chunk = TFv / nthr;               // 16
    const float* f0 = f0g + (size_t)b * TFv;

    for (int t = tid; t < TFv; t += nthr) s_f0[t] = f0[t];
    __syncthreads();

    const int base = tid * chunk;

    // ---- forward cummax of (voiced ? t : -1) ----
    {
        int run = -1;
        #pragma unroll
        for (int i = 0; i < chunk; ++i) {
            int t = base + i;
            if (s_f0[t] > 0.0f) run = t;
            s_prev[t] = run;
        }
        s_part[tid] = run;
    }
    __syncthreads();
    // inclusive max-scan over 512 partials
    #pragma unroll
    for (int off = 1; off < 512; off <<= 1) {
        int v = s_part[tid];
        int u = (tid >= off) ? s_part[tid - off] : -1;
        __syncthreads();
        s_part[tid] = (u > v) ? u : v;
        __syncthreads();
    }
    {
        int pre = (tid > 0) ? s_part[tid - 1] : -1;   // exclusive prefix max
        #pragma unroll
        for (int i = 0; i < chunk; ++i) {
            int t = base + i;
            if (s_prev[t] < pre) s_prev[t] = pre;
        }
    }
    __syncthreads();

    // ---- backward cummin of (voiced ? t : TF) ----
    {
        int run = TFv;
        #pragma unroll
        for (int i = chunk - 1; i >= 0; --i) {
            int t = base + i;
            if (s_f0[t] > 0.0f) run = t;
            s_next[t] = run;
        }
        s_part[tid] = run;
    }
    __syncthreads();
    // inclusive min-scan (suffix direction)
    #pragma unroll
    for (int off = 1; off < 512; off <<= 1) {
        int v = s_part[tid];
        int u = (tid + off < 512) ? s_part[tid + off] : TFv;
        __syncthreads();
        s_part[tid] = (u < v) ? u : v;
        __syncthreads();
    }
    {
        int suf = (tid < 511) ? s_part[tid + 1] : TFv;  // exclusive suffix min
        #pragma unroll
        for (int i = 0; i < chunk; ++i) {
            int t = base + i;
            if (s_next[t] > suf) s_next[t] = suf;
        }
    }
    __syncthreads();

    // linear interpolation of unvoiced frames (with edge clamping)
    for (int t = tid; t < TFv; t += nthr) {
        float f = s_f0[t];
        if (f > 0.0f) {
            s_a[t] = f;
        } else {
            int lo = s_prev[t], hi = s_next[t];
            int lo_t = (lo >= 0)  ? lo : hi;
            int hi_t = (hi < TFv) ? hi : lo;
            float lov = s_f0[lo_t];
            float hiv = s_f0[hi_t];
            int sp = hi_t - lo_t; if (sp < 1) sp = 1;
            float w = ((float)t - (float)lo_t) / (float)sp;
            w = fminf(fmaxf(w, 0.0f), 1.0f);
            s_a[t] = lov + w * (hiv - lov);
        }
    }
    __syncthreads();

    // Savitzky-Golay smooth (window 7, order 2), replicate padding
    {
        const float c0 = -2.0f / 21.0f, c1 = 3.0f / 21.0f, c2 = 6.0f / 21.0f, c3 = 7.0f / 21.0f;
        for (int t = tid; t < TFv; t += nthr) {
            int m1 = t-1 > 0 ? t-1 : 0;
            int m2 = t-2 > 0 ? t-2 : 0;
            int m3 = t-3 > 0 ? t-3 : 0;
            int p1 = t+1 < TFv-1 ? t+1 : TFv-1;
            int p2 = t+2 < TFv-1 ? t+2 : TFv-1;
            int p3 = t+3 < TFv-1 ? t+3 : TFv-1;
            float acc = c3 * s_a[t]
                      + c2 * (s_a[m1] + s_a[p1])
                      + c1 * (s_a[m2] + s_a[p2])
                      + c0 * (s_a[m3] + s_a[p3]);
            s_b[t] = acc;
        }
    }
    __syncthreads();

    // |second derivative| (replicate pad) and pair-fold to TF2, plus f0 pairs
    for (int j = tid; j < TF2v; j += nthr) {
        int t0 = 2 * j, t1 = 2 * j + 1;
        int t0m = t0 - 1 > 0 ? t0 - 1 : 0;
        int t1p = t1 + 1 < TFv - 1 ? t1 + 1 : TFv - 1;
        float d0 = fabsf(s_b[t0m] - 2.0f * s_b[t0] + s_b[t1]);
        float d1 = fabsf(s_b[t0]  - 2.0f * s_b[t1] + s_b[t1p]);
        g_d2pair[b * TF2v + j] = d0 + d1;
        g_f0pair[b * TF2v + j] = s_f0[t0] + s_f0[t1];
    }
}

// ---------------------------------------------------------------------------
// Kernel 2: the heavy one. 16 rows per block; each thread holds its slice of
// the d2pair/f0pair tables in REGISTERS (read once per block instead of once
// per row -> 16x less L2 table traffic; kernel becomes pure attn-stream DRAM
// bound). Per-row warp partials land in shared; single block sync at the end.
// ---------------------------------------------------------------------------
#define RPB 16   // rows per block
__global__ void __launch_bounds__(256) row_kernel(const float* __restrict__ attn,
                                                  float* __restrict__ out) {
    const int blk = blockIdx.x;            // 0 .. B*TP/RPB - 1  (512)
    const int b   = blk >> 5;              // 32 row-groups per batch
    const int rg  = blk & 31;
    const int tid = threadIdx.x;
    const int w   = tid >> 5, l = tid & 31;

    const float4* __restrict__ d2p = (const float4*)g_d2pair + (size_t)b * (TF2v / 4);
    const float4* __restrict__ f0p = (const float4*)g_f0pair + (size_t)b * (TF2v / 4);

    // register-resident tables: 4 float4 each (thread owns cols tid + 256*k)
    float4 d[4], f[4];
    #pragma unroll
    for (int k = 0; k < 4; ++k) {
        d[k] = d2p[tid + 256 * k];
        f[k] = f0p[tid + 256 * k];
    }

    __shared__ float red[RPB][3][8];

    const float4* __restrict__ base =
        (const float4*)attn + ((size_t)(b * TPv + rg * RPB)) * (TF2v / 4);

    #pragma unroll 2
    for (int r = 0; r < RPB; ++r) {
        const float4* __restrict__ row = base + (size_t)r * (TF2v / 4);
        float sa = 0.0f, sc = 0.0f, sm = 0.0f;
        #pragma unroll
        for (int k = 0; k < 4; ++k) {
            float4 a = row[tid + 256 * k];
            sa += (a.x + a.y) + (a.z + a.w);
            sc += a.x * d[k].x + a.y * d[k].y + a.z * d[k].z + a.w * d[k].w;
            sm += a.x * f[k].x + a.y * f[k].y + a.z * f[k].z + a.w * f[k].w;
        }
        #pragma unroll
        for (int o = 16; o > 0; o >>= 1) {
            sa += __shfl_down_sync(0xffffffffu, sa, o);
            sc += __shfl_down_sync(0xffffffffu, sc, o);
            sm += __shfl_down_sync(0xffffffffu, sm, o);
        }
        if (l == 0) { red[r][0][w] = sa; red[r][1][w] = sc; red[r][2][w] = sm; }
    }
    __syncthreads();

    if (tid < RPB) {
        float sa = 0.0f, sc = 0.0f, sm = 0.0f;
        #pragma unroll
        for (int i = 0; i < 8; ++i) {
            sa += red[tid][0][i]; sc += red[tid][1][i]; sm += red[tid][2][i];
        }
        float denom = fmaxf(2.0f * sa, 1.0f);
        float inv   = 1.0f / (denom + EPSv);
        int bid = b * TPv + rg * RPB + tid;
        out[bid]            = sc * inv;   // curv_phn
        out[Bv * TPv + bid] = sm * inv;   // mean_phn
    }
}

// ---------------------------------------------------------------------------
// Kernel 3 (fused): per-batch masked semitone-deficit energies (warp w owns
// batch w), then thread 0 does z-score, softmax(-z), B*wts, ESS. One launch.
// ---------------------------------------------------------------------------
__global__ void __launch_bounds__(512) tail_kernel(const float* __restrict__ uv,
                                                   float* __restrict__ out) {
    __shared__ float s_e[Bv];
    const int tid = threadIdx.x;
    const int w = tid >> 5, l = tid & 31;
    const int b = w;                          // 16 warps = 16 batches
    const float OODM =  21.688259064691245f;  // 12*log2(350/100)
    const float OODC = -71.589411415945055f;  // 12*log2(1.6/100)

    float dm = 0.0f, vm = 0.0f, dc = 0.0f, vc = 0.0f;
    #pragma unroll
    for (int k = 0; k < TPv / 32; ++k) {
        int p = l + 32 * k;
        float u  = uv[b * TPv + p];
        float cv = out[b * TPv + p];
        float mv = out[Bv * TPv + b * TPv + p];

        float pvm = mv * u;
        float vmi = (pvm != 0.0f) ? 1.0f : 0.0f;
        float semim = 12.0f * log2f(fmaxf(pvm, 1e-6f) * 0.01f);
        dm += fmaxf(OODM - semim, 0.0f) * vmi;
        vm += vmi;

        float pvc = cv * u;
        float vci = (pvc != 0.0f) ? 1.0f : 0.0f;
        float semic = 12.0f * log2f(fmaxf(pvc, 1e-6f) * 0.01f);
        dc += fmaxf(OODC - semic, 0.0f) * vci;
        vc += vci;
    }
    #pragma unroll
    for (int o = 16; o > 0; o >>= 1) {
        dm += __shfl_down_sync(0xffffffffu, dm, o);
        vm += __shfl_down_sync(0xffffffffu, vm, o);
        dc += __shfl_down_sync(0xffffffffu, dc, o);
        vc += __shfl_down_sync(0xffffffffu, vc, o);
    }
    if (l == 0) s_e[b] = dm / fmaxf(vm, 1.0f) + dc / fmaxf(vc, 1.0f);
    __syncthreads();

    if (tid == 0) {
        float e[Bv];
        float m = 0.0f;
        #pragma unroll
        for (int i = 0; i < Bv; ++i) { e[i] = s_e[i]; m += e[i]; }
        m /= (float)Bv;
        float var = 0.0f;
        #pragma unroll
        for (int i = 0; i < Bv; ++i) { float dd = e[i] - m; var += dd * dd; }
        var /= (float)Bv;
        float sd = fmaxf(sqrtf(var), 1e-6f);
        float x[Bv], mx = -1e30f;
        #pragma unroll
        for (int i = 0; i < Bv; ++i) { x[i] = -(e[i] - m) / sd; mx = fmaxf(mx, x[i]); }
        float s = 0.0f;
        #pragma unroll
        for (int i = 0; i < Bv; ++i) { x[i] = expf(x[i] - mx); s += x[i]; }
        float s2 = 0.0f;
        #pragma unroll
        for (int i = 0; i < Bv; ++i) { float wv = x[i] / s; x[i] = wv; s2 += wv * wv; }
        #pragma unroll
        for (int i = 0; i < Bv; ++i) out[2 * Bv * TPv + i] = (float)Bv * x[i];
        out[2 * Bv * TPv + Bv] = 1.0f / s2;
    }
}

// ---------------------------------------------------------------------------

extern "C" void kernel_launch(void* const* d_in, const int* in_sizes, int n_in,
                              void* d_out, int out_size) {
    const float* f0   = (const float*)d_in[0];   // [B, TF]
    const float* attn = (const float*)d_in[1];   // [B, TP, TF2]
    const float* uv   = (const float*)d_in[2];   // [B, TP]
    float* out = (float*)d_out;                  // curv | mean | B*wts | ess

    const size_t smem = (size_t)5 * TFv * sizeof(float); // 160 KB
    cudaFuncSetAttribute(frame_kernel, cudaFuncAttributeMaxDynamicSharedMemorySize, (int)smem);

    frame_kernel<<<Bv, 512, smem>>>(f0);
    row_kernel<<<(Bv * TPv) / RPB, 256>>>(attn, out);
    tail_kernel<<<1, 512>>>(uv, out);
}

// round 7
// speedup vs baseline: 1.2159x; 1.1298x over previous
#include <cuda_runtime.h>
#include <math.h>

#define TFv  8192
#define TF2v 4096
#define TPv  512
#define Bv   16
#define EPSv 1e-8f

// Scratch (no allocations allowed -> device globals)
__device__ float g_d2pair[Bv * TF2v];
__device__ float g_f0pair[Bv * TF2v];

// ---------------------------------------------------------------------------
// Kernel 1: per-batch frame pipeline: interp unvoiced -> SG smooth -> |d2|,
// then pair-fold to TF2 resolution. One block per batch, all in shared mem.
// Scans are hierarchical warp-shuffle scans (~10 barriers total, was ~40).
// ---------------------------------------------------------------------------
#define NT 1024
#define CHK (TFv / NT)   // 8
__global__ void __launch_bounds__(NT) frame_kernel(const float* __restrict__ f0g) {
    extern __shared__ char smem_raw[];
    float* s_f0  = (float*)smem_raw;            // original f0
    float* s_a   = s_f0  + TFv;                 // interpolated
    float* s_b   = s_a   + TFv;                 // smoothed
    int*   s_prev = (int*)(s_b + TFv);          // last voiced idx <= t
    int*   s_next = s_prev + TFv;               // first voiced idx >= t
    __shared__ int s_w[32];

    const int b    = blockIdx.x;
    const int tid  = threadIdx.x;
    const int lane = tid & 31;
    const int warp = tid >> 5;                  // 32 warps
    const unsigned FULL = 0xffffffffu;
    const float4* f0v = (const float4*)(f0g + (size_t)b * TFv);

    // vectorized load: 2048 float4, 1024 threads -> 2 iters
    {
        float4 v0 = f0v[tid];
        float4 v1 = f0v[tid + NT];
        ((float4*)s_f0)[tid]      = v0;
        ((float4*)s_f0)[tid + NT] = v1;
    }
    __syncthreads();

    const int base = tid * CHK;

    // ---- forward cummax of (voiced ? t : -1) ----
    int run = -1;
    #pragma unroll
    for (int i = 0; i < CHK; ++i) {
        int t = base + i;
        if (s_f0[t] > 0.0f) run = t;
        s_prev[t] = run;
    }
    // warp inclusive max-scan of per-thread partials
    int v = run;
    #pragma unroll
    for (int off = 1; off < 32; off <<= 1) {
        int u = __shfl_up_sync(FULL, v, off);
        if (lane >= off && u > v) v = u;
    }
    if (lane == 31) s_w[warp] = v;
    __syncthreads();
    if (warp == 0) {
        int x = s_w[lane];
        #pragma unroll
        for (int off = 1; off < 32; off <<= 1) {
            int u = __shfl_up_sync(FULL, x, off);
            if (lane >= off && u > x) x = u;
        }
        s_w[lane] = x;
    }
    __syncthreads();
    {
        int wpre = (warp > 0) ? s_w[warp - 1] : -1;
        int lp = __shfl_up_sync(FULL, v, 1);
        int epre = (lane > 0) ? lp : -1;
        int pre = (wpre > epre) ? wpre : epre;
        #pragma unroll
        for (int i = 0; i < CHK; ++i) {
            int t = base + i;
            if (s_prev[t] < pre) s_prev[t] = pre;
        }
    }
    __syncthreads();   // protect s_w before reuse

    // ---- backward cummin of (voiced ? t : TF) ----
    int runn = TFv;
    #pragma unroll
    for (int i = CHK - 1; i >= 0; --i) {
        int t = base + i;
        if (s_f0[t] > 0.0f) runn = t;
        s_next[t] = runn;
    }
    // warp inclusive min suffix-scan (high lane -> low lane)
    int v2 = runn;
    #pragma unroll
    for (int off = 1; off < 32; off <<= 1) {
        int u = __shfl_down_sync(FULL, v2, off);
        if (lane + off < 32 && u < v2) v2 = u;
    }
    if (lane == 0) s_w[warp] = v2;   // warp aggregate = min over warp
    __syncthreads();
    if (warp == 0) {
        int x = s_w[lane];
        #pragma unroll
        for (int off = 1; off < 32; off <<= 1) {
            int u = __shfl_down_sync(FULL, x, off);
            if (lane + off < 32 && u < x) x = u;
        }
        s_w[lane] = x;   // inclusive suffix over warp aggregates
    }
    __syncthreads();
    {
        int wsuf = (warp < 31) ? s_w[warp + 1] : TFv;
        int ln = __shfl_down_sync(FULL, v2, 1);
        int esuf = (lane < 31) ? ln : TFv;
        int suf = (wsuf < esuf) ? wsuf : esuf;
        #pragma unroll
        for (int i = 0; i < CHK; ++i) {
            int t = base + i;
            if (s_next[t] > suf) s_next[t] = suf;
        }
    }
    __syncthreads();

    // linear interpolation of unvoiced frames (with edge clamping)
    #pragma unroll
    for (int i = 0; i < CHK; ++i) {
        int t = base + i;
        float f = s_f0[t];
        if (f > 0.0f) {
            s_a[t] = f;
        } else {
            int lo = s_prev[t], hi = s_next[t];
            int lo_t = (lo >= 0)  ? lo : hi;
            int hi_t = (hi < TFv) ? hi : lo;
            float lov = s_f0[lo_t];
            float hiv = s_f0[hi_t];
            int sp = hi_t - lo_t; if (sp < 1) sp = 1;
            float w = ((float)t - (float)lo_t) / (float)sp;
            w = fminf(fmaxf(w, 0.0f), 1.0f);
            s_a[t] = lov + w * (hiv - lov);
        }
    }
    __syncthreads();

    // Savitzky-Golay smooth (window 7, order 2), replicate padding
    {
        const float c0 = -2.0f / 21.0f, c1 = 3.0f / 21.0f, c2 = 6.0f / 21.0f, c3 = 7.0f / 21.0f;
        #pragma unroll
        for (int i = 0; i < CHK; ++i) {
            int t = base + i;
            int m1 = t-1 > 0 ? t-1 : 0;
            int m2 = t-2 > 0 ? t-2 : 0;
            int m3 = t-3 > 0 ? t-3 : 0;
            int p1 = t+1 < TFv-1 ? t+1 : TFv-1;
            int p2 = t+2 < TFv-1 ? t+2 : TFv-1;
            int p3 = t+3 < TFv-1 ? t+3 : TFv-1;
            s_b[t] = c3 * s_a[t]
                   + c2 * (s_a[m1] + s_a[p1])
                   + c1 * (s_a[m2] + s_a[p2])
                   + c0 * (s_a[m3] + s_a[p3]);
        }
    }
    __syncthreads();

    // |second derivative| (replicate pad) and pair-fold to TF2, plus f0 pairs
    #pragma unroll
    for (int i = 0; i < CHK / 2; ++i) {
        int j = tid * (CHK / 2) + i;
        int t0 = 2 * j, t1 = 2 * j + 1;
        int t0m = t0 - 1 > 0 ? t0 - 1 : 0;
        int t1p = t1 + 1 < TFv - 1 ? t1 + 1 : TFv - 1;
        float d0 = fabsf(s_b[t0m] - 2.0f * s_b[t0] + s_b[t1]);
        float d1 = fabsf(s_b[t0]  - 2.0f * s_b[t1] + s_b[t1p]);
        g_d2pair[b * TF2v + j] = d0 + d1;
        g_f0pair[b * TF2v + j] = s_f0[t0] + s_f0[t1];
    }
}

// ---------------------------------------------------------------------------
// Kernel 2: the heavy one. 16 rows per block; each thread holds its slice of
// the d2pair/f0pair tables in REGISTERS (read once per block instead of once
// per row). Per-row warp partials land in shared; single block sync at end.
// ---------------------------------------------------------------------------
#define RPB 16   // rows per block
__global__ void __launch_bounds__(256) row_kernel(const float* __restrict__ attn,
                                                  float* __restrict__ out) {
    const int blk = blockIdx.x;            // 0 .. B*TP/RPB - 1  (512)
    const int b   = blk >> 5;              // 32 row-groups per batch
    const int rg  = blk & 31;
    const int tid = threadIdx.x;
    const int w   = tid >> 5, l = tid & 31;

    const float4* __restrict__ d2p = (const float4*)g_d2pair + (size_t)b * (TF2v / 4);
    const float4* __restrict__ f0p = (const float4*)g_f0pair + (size_t)b * (TF2v / 4);

    float4 d[4], f[4];
    #pragma unroll
    for (int k = 0; k < 4; ++k) {
        d[k] = d2p[tid + 256 * k];
        f[k] = f0p[tid + 256 * k];
    }

    __shared__ float red[RPB][3][8];

    const float4* __restrict__ base =
        (const float4*)attn + ((size_t)(b * TPv + rg * RPB)) * (TF2v / 4);

    #pragma unroll 2
    for (int r = 0; r < RPB; ++r) {
        const float4* __restrict__ row = base + (size_t)r * (TF2v / 4);
        float sa = 0.0f, sc = 0.0f, sm = 0.0f;
        #pragma unroll
        for (int k = 0; k < 4; ++k) {
            float4 a = row[tid + 256 * k];
            sa += (a.x + a.y) + (a.z + a.w);
            sc += a.x * d[k].x + a.y * d[k].y + a.z * d[k].z + a.w * d[k].w;
            sm += a.x * f[k].x + a.y * f[k].y + a.z * f[k].z + a.w * f[k].w;
        }
        #pragma unroll
        for (int o = 16; o > 0; o >>= 1) {
            sa += __shfl_down_sync(0xffffffffu, sa, o);
            sc += __shfl_down_sync(0xffffffffu, sc, o);
            sm += __shfl_down_sync(0xffffffffu, sm, o);
        }
        if (l == 0) { red[r][0][w] = sa; red[r][1][w] = sc; red[r][2][w] = sm; }
    }
    __syncthreads();

    if (tid < RPB) {
        float sa = 0.0f, sc = 0.0f, sm = 0.0f;
        #pragma unroll
        for (int i = 0; i < 8; ++i) {
            sa += red[tid][0][i]; sc += red[tid][1][i]; sm += red[tid][2][i];
        }
        float denom = fmaxf(2.0f * sa, 1.0f);
        float inv   = 1.0f / (denom + EPSv);
        int bid = b * TPv + rg * RPB + tid;
        out[bid]            = sc * inv;   // curv_phn
        out[Bv * TPv + bid] = sm * inv;   // mean_phn
    }
}

// ---------------------------------------------------------------------------
// Kernel 3 (fused): per-batch masked semitone-deficit energies (warp w owns
// batch w), then thread 0 does z-score, softmax(-z), B*wts, ESS. One launch.
// ---------------------------------------------------------------------------
__global__ void __launch_bounds__(512) tail_kernel(const float* __restrict__ uv,
                                                   float* __restrict__ out) {
    __shared__ float s_e[Bv];
    const int tid = threadIdx.x;
    const int w = tid >> 5, l = tid & 31;
    const int b = w;                          // 16 warps = 16 batches
    const float OODM =  21.688259064691245f;  // 12*log2(350/100)
    const float OODC = -71.589411415945055f;  // 12*log2(1.6/100)

    float dm = 0.0f, vm = 0.0f, dc = 0.0f, vc = 0.0f;
    #pragma unroll
    for (int k = 0; k < TPv / 32; ++k) {
        int p = l + 32 * k;
        float u  = uv[b * TPv + p];
        float cv = out[b * TPv + p];
        float mv = out[Bv * TPv + b * TPv + p];

        float pvm = mv * u;
        float vmi = (pvm != 0.0f) ? 1.0f : 0.0f;
        float semim = 12.0f * log2f(fmaxf(pvm, 1e-6f) * 0.01f);
        dm += fmaxf(OODM - semim, 0.0f) * vmi;
        vm += vmi;

        float pvc = cv * u;
        float vci = (pvc != 0.0f) ? 1.0f : 0.0f;
        float semic = 12.0f * log2f(fmaxf(pvc, 1e-6f) * 0.01f);
        dc += fmaxf(OODC - semic, 0.0f) * vci;
        vc += vci;
    }
    #pragma unroll
    for (int o = 16; o > 0; o >>= 1) {
        dm += __shfl_down_sync(0xffffffffu, dm, o);
        vm += __shfl_down_sync(0xffffffffu, vm, o);
        dc += __shfl_down_sync(0xffffffffu, dc, o);
        vc += __shfl_down_sync(0xffffffffu, vc, o);
    }
    if (l == 0) s_e[b] = dm / fmaxf(vm, 1.0f) + dc / fmaxf(vc, 1.0f);
    __syncthreads();

    if (tid == 0) {
        float e[Bv];
        float m = 0.0f;
        #pragma unroll
        for (int i = 0; i < Bv; ++i) { e[i] = s_e[i]; m += e[i]; }
        m /= (float)Bv;
        float var = 0.0f;
        #pragma unroll
        for (int i = 0; i < Bv; ++i) { float dd = e[i] - m; var += dd * dd; }
        var /= (float)Bv;
        float sd = fmaxf(sqrtf(var), 1e-6f);
        float x[Bv], mx = -1e30f;
        #pragma unroll
        for (int i = 0; i < Bv; ++i) { x[i] = -(e[i] - m) / sd; mx = fmaxf(mx, x[i]); }
        float s = 0.0f;
        #pragma unroll
        for (int i = 0; i < Bv; ++i) { x[i] = expf(x[i] - mx); s += x[i]; }
        float s2 = 0.0f;
        #pragma unroll
        for (int i = 0; i < Bv; ++i) { float wv = x[i] / s; x[i] = wv; s2 += wv * wv; }
        #pragma unroll
        for (int i = 0; i < Bv; ++i) out[2 * Bv * TPv + i] = (float)Bv * x[i];
        out[2 * Bv * TPv + Bv] = 1.0f / s2;
    }
}

// ---------------------------------------------------------------------------

extern "C" void kernel_launch(void* const* d_in, const int* in_sizes, int n_in,
                              void* d_out, int out_size) {
    const float* f0   = (const float*)d_in[0];   // [B, TF]
    const float* attn = (const float*)d_in[1];   // [B, TP, TF2]
    const float* uv   = (const float*)d_in[2];   // [B, TP]
    float* out = (float*)d_out;                  // curv | mean | B*wts | ess

    const size_t smem = (size_t)5 * TFv * sizeof(float); // 160 KB
    cudaFuncSetAttribute(frame_kernel, cudaFuncAttributeMaxDynamicSharedMemorySize, (int)smem);

    frame_kernel<<<Bv, NT, smem>>>(f0);
    row_kernel<<<(Bv * TPv) / RPB, 256>>>(attn, out);
    tail_kernel<<<1, 512>>>(uv, out);
}

// round 9
// speedup vs baseline: 1.4125x; 1.1617x over previous
#include <cuda_runtime.h>
#include <math.h>

#define TFv  8192
#define TF2v 4096
#define TPv  512
#define Bv   16
#define EPSv 1e-8f

// Scratch (no allocations allowed -> device globals)
__device__ float g_d2pair[Bv * TF2v];
__device__ float g_f0pair[Bv * TF2v];
__device__ unsigned g_ctr = 0;   // last-block-does-tail counter (self-resetting)

// ---------------------------------------------------------------------------
// Kernel 1: segment-parallel frame pipeline.
// Grid = B * 32 blocks; each block handles 256 output frames of one batch,
// with a +-128 frame halo in smem. interp seeds outside the halo come from a
// warp-level global search (exact; terminates because f0[:,0] is voiced).
// ---------------------------------------------------------------------------
#define SEG   256
#define HALO  128
#define EXTN  512                 // [start-128, start+384)
#define ABASE 120                 // s_a/s_b cover ext indices [120, 392) = t in [start-8, start+264)
#define ASZ   272

__global__ void __launch_bounds__(256) frame_kernel(const float* __restrict__ f0g) {
    __shared__ float s_f0[EXTN];
    __shared__ float s_a[ASZ];
    __shared__ float s_b[ASZ];
    __shared__ int   s_prev[EXTN];
    __shared__ int   s_next[EXTN];
    __shared__ int   s_wA[8], s_wB[8];
    __shared__ int   s_seed[2];

    const int blk   = blockIdx.x;
    const int b     = blk >> 5;
    const int seg   = blk & 31;
    const int start = seg * SEG;
    const int EB    = start - HALO;          // ext base (global frame index of ext slot 0)
    const int tid   = threadIdx.x;
    const int lane  = tid & 31;
    const int warp  = tid >> 5;              // 8 warps
    const unsigned FULL = 0xffffffffu;
    const float* __restrict__ f0row = f0g + (size_t)b * TFv;

    // ---- load ext window (replicate-clamped at global edges) ----
    #pragma unroll
    for (int i = tid; i < EXTN; i += 256) {
        int g = EB + i;
        int gc = g < 0 ? 0 : (g > TFv - 1 ? TFv - 1 : g);
        s_f0[i] = f0row[gc];
    }

    // ---- seeds: last voiced < EB (warp 0), first voiced >= EB+EXTN (warp 1) ----
    if (warp == 0) {
        int found = -1;
        for (int g0 = EB - 1; g0 >= 0 && found < 0; g0 -= 32) {
            int g = g0 - lane;
            bool v = (g >= 0) && (f0row[g] > 0.0f);
            unsigned m = __ballot_sync(FULL, v);
            if (m) found = g0 - (__ffs(m) - 1);   // smallest lane = largest index
        }
        if (lane == 0) s_seed[0] = found;
    } else if (warp == 1) {
        int found = TFv;
        for (int g0 = EB + EXTN; g0 < TFv && found == TFv; g0 += 32) {
            int g = g0 + lane;
            bool v = (g < TFv) && (f0row[g] > 0.0f);
            unsigned m = __ballot_sync(FULL, v);
            if (m) found = g0 + (__ffs(m) - 1);   // smallest lane = smallest index
        }
        if (lane == 0) s_seed[1] = found;
    }
    __syncthreads();                                            // (1)

    const int li0 = 2 * tid;                 // each thread owns ext slots li0, li0+1
    const int g0i = EB + li0;

    // ---- forward cummax of (voiced ? global_idx : -1) over ext ----
    int run = -1;
    if (s_f0[li0]     > 0.0f) run = g0i;
    s_prev[li0] = run;
    if (s_f0[li0 + 1] > 0.0f) run = g0i + 1;
    s_prev[li0 + 1] = run;
    int v = run;
    #pragma unroll
    for (int off = 1; off < 32; off <<= 1) {
        int u = __shfl_up_sync(FULL, v, off);
        if (lane >= off && u > v) v = u;
    }
    if (lane == 31) s_wA[warp] = v;
    __syncthreads();                                            // (2)
    if (warp == 0 && lane < 8) {
        int x = s_wA[lane];
        #pragma unroll
        for (int off = 1; off < 8; off <<= 1) {
            int u = __shfl_up_sync(0xffu, x, off);
            if (lane >= off && u > x) x = u;
        }
        s_wA[lane] = x;
    }
    __syncthreads();                                            // (3)
    {
        int wpre = (warp > 0) ? s_wA[warp - 1] : -1;
        int lp = __shfl_up_sync(FULL, v, 1);
        int epre = (lane > 0) ? lp : -1;
        int pre = (wpre > epre) ? wpre : epre;
        int sd = s_seed[0];
        if (sd > pre) pre = sd;
        if (s_prev[li0]     < pre) s_prev[li0]     = pre;
        // inclusive value for slot li0 also bounds slot li0+1 via 'run' chain already stored
        int pre1 = (s_prev[li0] > pre) ? s_prev[li0] : pre;
        if (s_prev[li0 + 1] < pre1) s_prev[li0 + 1] = pre1;
    }

    // ---- backward cummin of (voiced ? global_idx : TFv) over ext ----
    int runn = TFv;
    if (s_f0[li0 + 1] > 0.0f) runn = g0i + 1;
    s_next[li0 + 1] = runn;
    if (s_f0[li0]     > 0.0f) runn = g0i;
    s_next[li0] = runn;
    int v2 = runn;
    #pragma unroll
    for (int off = 1; off < 32; off <<= 1) {
        int u = __shfl_down_sync(FULL, v2, off);
        if (lane + off < 32 && u < v2) v2 = u;
    }
    if (lane == 0) s_wB[warp] = v2;
    __syncthreads();                                            // (4)
    if (warp == 0 && lane < 8) {
        int x = s_wB[lane];
        #pragma unroll
        for (int off = 1; off < 8; off <<= 1) {
            int u = __shfl_down_sync(0xffu, x, off);
            if (lane + off < 8 && u < x) x = u;
        }
        s_wB[lane] = x;
    }
    __syncthreads();                                            // (5)
    {
        int wsuf = (warp < 7) ? s_wB[warp + 1] : TFv;
        int ln = __shfl_down_sync(FULL, v2, 1);
        int esuf = (lane < 31) ? ln : TFv;
        int suf = (wsuf < esuf) ? wsuf : esuf;
        int sd = s_seed[1];
        if (sd < suf) suf = sd;
        if (s_next[li0 + 1] > suf) s_next[li0 + 1] = suf;
        int suf0 = (s_next[li0 + 1] < suf) ? s_next[li0 + 1] : suf;
        if (s_next[li0] > suf0) s_next[li0] = suf0;
    }
    __syncthreads();                                            // (6)

    // ---- interp unvoiced for t in [start-8, start+264) ∩ [0, TFv) ----
    #pragma unroll
    for (int i = tid; i < ASZ; i += 256) {
        int t = EB + ABASE + i;
        if (t < 0 || t >= TFv) continue;
        int li = ABASE + i;
        float f = s_f0[li];
        if (f > 0.0f) {
            s_a[i] = f;
        } else {
            int lo = s_prev[li], hi = s_next[li];
            int lo_t = (lo >= 0)  ? lo : hi;
            int hi_t = (hi < TFv) ? hi : lo;
            float lov = f0row[lo_t];
            float hiv = f0row[hi_t];
            int sp = hi_t - lo_t; if (sp < 1) sp = 1;
            float w = ((float)t - (float)lo_t) / (float)sp;
            w = fminf(fmaxf(w, 0.0f), 1.0f);
            s_a[i] = lov + w * (hiv - lov);
        }
    }
    __syncthreads();                                            // (7)

    // ---- SG smooth for t in [start-1, start+257): s_a idx = t-start+8 ----
    {
        const float c0 = -2.0f / 21.0f, c1 = 3.0f / 21.0f, c2 = 6.0f / 21.0f, c3 = 7.0f / 21.0f;
        #pragma unroll
        for (int i = 7 + tid; i < 265; i += 256) {
            int t = (start - 8) + i;
            int m1 = t-1 > 0 ? t-1 : 0;
            int m2 = t-2 > 0 ? t-2 : 0;
            int m3 = t-3 > 0 ? t-3 : 0;
            int p1 = t+1 < TFv-1 ? t+1 : TFv-1;
            int p2 = t+2 < TFv-1 ? t+2 : TFv-1;
            int p3 = t+3 < TFv-1 ? t+3 : TFv-1;
            int off = start - 8;
            s_b[i] = c3 * s_a[t - off]
                   + c2 * (s_a[m1 - off] + s_a[p1 - off])
                   + c1 * (s_a[m2 - off] + s_a[p2 - off])
                   + c0 * (s_a[m3 - off] + s_a[p3 - off]);
        }
    }
    __syncthreads();                                            // (8)

    // ---- |d2| + pair-fold: 128 output pairs for this segment ----
    if (tid < 128) {
        int j  = (start >> 1) + tid;
        int t0 = 2 * j, t1 = t0 + 1;
        int t0m = t0 - 1 > 0 ? t0 - 1 : 0;
        int t1p = t1 + 1 < TFv - 1 ? t1 + 1 : TFv - 1;
        int off = start - 8;
        float b0 = s_b[t0 - off], b1 = s_b[t1 - off];
        float d0 = fabsf(s_b[t0m - off] - 2.0f * b0 + b1);
        float d1 = fabsf(b0 - 2.0f * b1 + s_b[t1p - off]);
        g_d2pair[b * TF2v + j] = d0 + d1;
        g_f0pair[b * TF2v + j] = s_f0[(t0 - EB)] + s_f0[(t1 - EB)];
    }
}

// ---------------------------------------------------------------------------
// Kernel 2: heavy kernel + fused tail. 16 rows per block; register-resident
// d2/f0 tables. The last block to finish (atomic counter) computes the
// per-batch energies, z-score, softmax(-z), B*wts and ESS.
// ---------------------------------------------------------------------------
#define RPB 16
__global__ void __launch_bounds__(256) row_kernel(const float* __restrict__ attn,
                                                  const float* __restrict__ uv,
                                                  float* __restrict__ out) {
    const int blk = blockIdx.x;            // 0 .. 511
    const int b   = blk >> 5;
    const int rg  = blk & 31;
    const int tid = threadIdx.x;
    const int w   = tid >> 5, l = tid & 31;

    const float4* __restrict__ d2p = (const float4*)g_d2pair + (size_t)b * (TF2v / 4);
    const float4* __restrict__ f0p = (const float4*)g_f0pair + (size_t)b * (TF2v / 4);

    float4 d[4], f[4];
    #pragma unroll
    for (int k = 0; k < 4; ++k) {
        d[k] = d2p[tid + 256 * k];
        f[k] = f0p[tid + 256 * k];
    }

    __shared__ float red[RPB][3][8];
    __shared__ int   s_last;
    __shared__ float s_e[Bv];

    const float4* __restrict__ base =
        (const float4*)attn + ((size_t)(b * TPv + rg * RPB)) * (TF2v / 4);

    #pragma unroll 2
    for (int r = 0; r < RPB; ++r) {
        const float4* __restrict__ row = base + (size_t)r * (TF2v / 4);
        float sa = 0.0f, sc = 0.0f, sm = 0.0f;
        #pragma unroll
        for (int k = 0; k < 4; ++k) {
            float4 a = row[tid + 256 * k];
            sa += (a.x + a.y) + (a.z + a.w);
            sc += a.x * d[k].x + a.y * d[k].y + a.z * d[k].z + a.w * d[k].w;
            sm += a.x * f[k].x + a.y * f[k].y + a.z * f[k].z + a.w * f[k].w;
        }
        #pragma unroll
        for (int o = 16; o > 0; o >>= 1) {
            sa += __shfl_down_sync(0xffffffffu, sa, o);
            sc += __shfl_down_sync(0xffffffffu, sc, o);
            sm += __shfl_down_sync(0xffffffffu, sm, o);
        }
        if (l == 0) { red[r][0][w] = sa; red[r][1][w] = sc; red[r][2][w] = sm; }
    }
    __syncthreads();

    if (tid < RPB) {
        float sa = 0.0f, sc = 0.0f, sm = 0.0f;
        #pragma unroll
        for (int i = 0; i < 8; ++i) {
            sa += red[tid][0][i]; sc += red[tid][1][i]; sm += red[tid][2][i];
        }
        float denom = fmaxf(2.0f * sa, 1.0f);
        float inv   = 1.0f / (denom + EPSv);
        int bid = b * TPv + rg * RPB + tid;
        out[bid]            = sc * inv;   // curv_phn
        out[Bv * TPv + bid] = sm * inv;   // mean_phn
    }

    // ---- last-block epilogue ----
    __threadfence();                       // release our out[] writes
    __syncthreads();
    if (tid == 0) {
        unsigned old = atomicAdd(&g_ctr, 1u);
        s_last = (old == (unsigned)(gridDim.x - 1)) ? 1 : 0;
    }
    __syncthreads();
    if (!s_last) return;
    if (tid == 0) g_ctr = 0;               // reset for next graph replay
    __threadfence();                       // acquire: all blocks' out[] visible

    const float OODM =  21.688259064691245f;   // 12*log2(350/100)
    const float OODC = -71.589411415945055f;   // 12*log2(1.6/100)

    // 8 warps, each handles 2 batches
    #pragma unroll
    for (int pass = 0; pass < 2; ++pass) {
        int bb = w + 8 * pass;
        float dm = 0.0f, vm = 0.0f, dc = 0.0f, vc = 0.0f;
        #pragma unroll
        for (int k = 0; k < TPv / 32; ++k) {
            int p = l + 32 * k;
            float u  = uv[bb * TPv + p];
            float cv = out[bb * TPv + p];
            float mv = out[Bv * TPv + bb * TPv + p];

            float pvm = mv * u;
            float vmi = (pvm != 0.0f) ? 1.0f : 0.0f;
            float semim = 12.0f * log2f(fmaxf(pvm, 1e-6f) * 0.01f);
            dm += fmaxf(OODM - semim, 0.0f) * vmi;
            vm += vmi;

            float pvc = cv * u;
            float vci = (pvc != 0.0f) ? 1.0f : 0.0f;
            float semic = 12.0f * log2f(fmaxf(pvc, 1e-6f) * 0.01f);
            dc += fmaxf(OODC - semic, 0.0f) * vci;
            vc += vci;
        }
        #pragma unroll
        for (int o = 16; o > 0; o >>= 1) {
            dm += __shfl_down_sync(0xffffffffu, dm, o);
            vm += __shfl_down_sync(0xffffffffu, vm, o);
            dc += __shfl_down_sync(0xffffffffu, dc, o);
            vc += __shfl_down_sync(0xffffffffu, vc, o);
        }
        if (l == 0) s_e[bb] = dm / fmaxf(vm, 1.0f) + dc / fmaxf(vc, 1.0f);
    }
    __syncthreads();

    if (tid == 0) {
        float e[Bv];
        float m = 0.0f;
        #pragma unroll
        for (int i = 0; i < Bv; ++i) { e[i] = s_e[i]; m += e[i]; }
        m /= (float)Bv;
        float var = 0.0f;
        #pragma unroll
        for (int i = 0; i < Bv; ++i) { float dd = e[i] - m; var += dd * dd; }
        var /= (float)Bv;
        float sd = fmaxf(sqrtf(var), 1e-6f);
        float x[Bv], mx = -1e30f;
        #pragma unroll
        for (int i = 0; i < Bv; ++i) { x[i] = -(e[i] - m) / sd; mx = fmaxf(mx, x[i]); }
        float s = 0.0f;
        #pragma unroll
        for (int i = 0; i < Bv; ++i) { x[i] = expf(x[i] - mx); s += x[i]; }
        float s2 = 0.0f;
        #pragma unroll
        for (int i = 0; i < Bv; ++i) { float wv = x[i] / s; x[i] = wv; s2 += wv * wv; }
        #pragma unroll
        for (int i = 0; i < Bv; ++i) out[2 * Bv * TPv + i] = (float)Bv * x[i];
        out[2 * Bv * TPv + Bv] = 1.0f / s2;
    }
}

// ---------------------------------------------------------------------------

extern "C" void kernel_launch(void* const* d_in, const int* in_sizes, int n_in,
                              void* d_out, int out_size) {
    const float* f0   = (const float*)d_in[0];   // [B, TF]
    const float* attn = (const float*)d_in[1];   // [B, TP, TF2]
    const float* uv   = (const float*)d_in[2];   // [B, TP]
    float* out = (float*)d_out;                  // curv | mean | B*wts | ess

    frame_kernel<<<Bv * 32, 256>>>(f0);
    row_kernel<<<(Bv * TPv) / RPB, 256>>>(attn, uv, out);
}

// round 10
// speedup vs baseline: 1.4747x; 1.0440x over previous
#include <cuda_runtime.h>
#include <math.h>

#define TFv  8192
#define TF2v 4096
#define TPv  512
#define Bv   16
#define EPSv 1e-8f

// Scratch (no allocations allowed -> device globals)
__device__ float g_d2pair[Bv * TF2v];
__device__ float g_f0pair[Bv * TF2v];
__device__ unsigned g_ctr = 0;   // last-block-does-tail counter (self-resetting)

// ---------------------------------------------------------------------------
// Kernel 1: segment-parallel frame pipeline (unchanged from R7; ~4.6us).
// ---------------------------------------------------------------------------
#define SEG   256
#define HALO  128
#define EXTN  512
#define ABASE 120
#define ASZ   272

__global__ void __launch_bounds__(256) frame_kernel(const float* __restrict__ f0g) {
    __shared__ float s_f0[EXTN];
    __shared__ float s_a[ASZ];
    __shared__ float s_b[ASZ];
    __shared__ int   s_prev[EXTN];
    __shared__ int   s_next[EXTN];
    __shared__ int   s_wA[8], s_wB[8];
    __shared__ int   s_seed[2];

    const int blk   = blockIdx.x;
    const int b     = blk >> 5;
    const int seg   = blk & 31;
    const int start = seg * SEG;
    const int EB    = start - HALO;
    const int tid   = threadIdx.x;
    const int lane  = tid & 31;
    const int warp  = tid >> 5;
    const unsigned FULL = 0xffffffffu;
    const float* __restrict__ f0row = f0g + (size_t)b * TFv;

    #pragma unroll
    for (int i = tid; i < EXTN; i += 256) {
        int g = EB + i;
        int gc = g < 0 ? 0 : (g > TFv - 1 ? TFv - 1 : g);
        s_f0[i] = f0row[gc];
    }

    if (warp == 0) {
        int found = -1;
        for (int g0 = EB - 1; g0 >= 0 && found < 0; g0 -= 32) {
            int g = g0 - lane;
            bool v = (g >= 0) && (f0row[g] > 0.0f);
            unsigned m = __ballot_sync(FULL, v);
            if (m) found = g0 - (__ffs(m) - 1);
        }
        if (lane == 0) s_seed[0] = found;
    } else if (warp == 1) {
        int found = TFv;
        for (int g0 = EB + EXTN; g0 < TFv && found == TFv; g0 += 32) {
            int g = g0 + lane;
            bool v = (g < TFv) && (f0row[g] > 0.0f);
            unsigned m = __ballot_sync(FULL, v);
            if (m) found = g0 + (__ffs(m) - 1);
        }
        if (lane == 0) s_seed[1] = found;
    }
    __syncthreads();

    const int li0 = 2 * tid;
    const int g0i = EB + li0;

    int run = -1;
    if (s_f0[li0]     > 0.0f) run = g0i;
    s_prev[li0] = run;
    if (s_f0[li0 + 1] > 0.0f) run = g0i + 1;
    s_prev[li0 + 1] = run;
    int v = run;
    #pragma unroll
    for (int off = 1; off < 32; off <<= 1) {
        int u = __shfl_up_sync(FULL, v, off);
        if (lane >= off && u > v) v = u;
    }
    if (lane == 31) s_wA[warp] = v;
    __syncthreads();
    if (warp == 0 && lane < 8) {
        int x = s_wA[lane];
        #pragma unroll
        for (int off = 1; off < 8; off <<= 1) {
            int u = __shfl_up_sync(0xffu, x, off);
            if (lane >= off && u > x) x = u;
        }
        s_wA[lane] = x;
    }
    __syncthreads();
    {
        int wpre = (warp > 0) ? s_wA[warp - 1] : -1;
        int lp = __shfl_up_sync(FULL, v, 1);
        int epre = (lane > 0) ? lp : -1;
        int pre = (wpre > epre) ? wpre : epre;
        int sd = s_seed[0];
        if (sd > pre) pre = sd;
        if (s_prev[li0]     < pre) s_prev[li0]     = pre;
        int pre1 = (s_prev[li0] > pre) ? s_prev[li0] : pre;
        if (s_prev[li0 + 1] < pre1) s_prev[li0 + 1] = pre1;
    }

    int runn = TFv;
    if (s_f0[li0 + 1] > 0.0f) runn = g0i + 1;
    s_next[li0 + 1] = runn;
    if (s_f0[li0]     > 0.0f) runn = g0i;
    s_next[li0] = runn;
    int v2 = runn;
    #pragma unroll
    for (int off = 1; off < 32; off <<= 1) {
        int u = __shfl_down_sync(FULL, v2, off);
        if (lane + off < 32 && u < v2) v2 = u;
    }
    if (lane == 0) s_wB[warp] = v2;
    __syncthreads();
    if (warp == 0 && lane < 8) {
        int x = s_wB[lane];
        #pragma unroll
        for (int off = 1; off < 8; off <<= 1) {
            int u = __shfl_down_sync(0xffu, x, off);
            if (lane + off < 8 && u < x) x = u;
        }
        s_wB[lane] = x;
    }
    __syncthreads();
    {
        int wsuf = (warp < 7) ? s_wB[warp + 1] : TFv;
        int ln = __shfl_down_sync(FULL, v2, 1);
        int esuf = (lane < 31) ? ln : TFv;
        int suf = (wsuf < esuf) ? wsuf : esuf;
        int sd = s_seed[1];
        if (sd < suf) suf = sd;
        if (s_next[li0 + 1] > suf) s_next[li0 + 1] = suf;
        int suf0 = (s_next[li0 + 1] < suf) ? s_next[li0 + 1] : suf;
        if (s_next[li0] > suf0) s_next[li0] = suf0;
    }
    __syncthreads();

    #pragma unroll
    for (int i = tid; i < ASZ; i += 256) {
        int t = EB + ABASE + i;
        if (t < 0 || t >= TFv) continue;
        int li = ABASE + i;
        float f = s_f0[li];
        if (f > 0.0f) {
            s_a[i] = f;
        } else {
            int lo = s_prev[li], hi = s_next[li];
            int lo_t = (lo >= 0)  ? lo : hi;
            int hi_t = (hi < TFv) ? hi : lo;
            float lov = f0row[lo_t];
            float hiv = f0row[hi_t];
            int sp = hi_t - lo_t; if (sp < 1) sp = 1;
            float w = ((float)t - (float)lo_t) / (float)sp;
            w = fminf(fmaxf(w, 0.0f), 1.0f);
            s_a[i] = lov + w * (hiv - lov);
        }
    }
    __syncthreads();

    {
        const float c0 = -2.0f / 21.0f, c1 = 3.0f / 21.0f, c2 = 6.0f / 21.0f, c3 = 7.0f / 21.0f;
        #pragma unroll
        for (int i = 7 + tid; i < 265; i += 256) {
            int t = (start - 8) + i;
            int m1 = t-1 > 0 ? t-1 : 0;
            int m2 = t-2 > 0 ? t-2 : 0;
            int m3 = t-3 > 0 ? t-3 : 0;
            int p1 = t+1 < TFv-1 ? t+1 : TFv-1;
            int p2 = t+2 < TFv-1 ? t+2 : TFv-1;
            int p3 = t+3 < TFv-1 ? t+3 : TFv-1;
            int off = start - 8;
            s_b[i] = c3 * s_a[t - off]
                   + c2 * (s_a[m1 - off] + s_a[p1 - off])
                   + c1 * (s_a[m2 - off] + s_a[p2 - off])
                   + c0 * (s_a[m3 - off] + s_a[p3 - off]);
        }
    }
    __syncthreads();

    if (tid < 128) {
        int j  = (start >> 1) + tid;
        int t0 = 2 * j, t1 = t0 + 1;
        int t0m = t0 - 1 > 0 ? t0 - 1 : 0;
        int t1p = t1 + 1 < TFv - 1 ? t1 + 1 : TFv - 1;
        int off = start - 8;
        float b0 = s_b[t0 - off], b1 = s_b[t1 - off];
        float d0 = fabsf(s_b[t0m - off] - 2.0f * b0 + b1);
        float d1 = fabsf(b0 - 2.0f * b1 + s_b[t1p - off]);
        g_d2pair[b * TF2v + j] = d0 + d1;
        g_f0pair[b * TF2v + j] = s_f0[(t0 - EB)] + s_f0[(t1 - EB)];
    }
}

// ---------------------------------------------------------------------------
// Kernel 2: heavy kernel + fused tail.
// Tables now live in SHARED memory (regs 60 -> ~40 => occupancy up => MLP up).
// Inner loop processes 2 rows at once (2 independent LDG streams).
// attn loads use __ldcs (streaming, evict-first): read-once data.
// ---------------------------------------------------------------------------
#define RPB 16
__global__ void __launch_bounds__(256) row_kernel(const float* __restrict__ attn,
                                                  const float* __restrict__ uv,
                                                  float* __restrict__ out) {
    const int blk = blockIdx.x;            // 0 .. 511
    const int b   = blk >> 5;
    const int rg  = blk & 31;
    const int tid = threadIdx.x;
    const int w   = tid >> 5, l = tid & 31;

    __shared__ float4 s_d[TF2v / 4];       // 16 KB
    __shared__ float4 s_f[TF2v / 4];       // 16 KB
    __shared__ float  red[RPB][3][8];
    __shared__ int    s_last;
    __shared__ float  s_e[Bv];

    {
        const float4* __restrict__ d2p = (const float4*)g_d2pair + (size_t)b * (TF2v / 4);
        const float4* __restrict__ f0p = (const float4*)g_f0pair + (size_t)b * (TF2v / 4);
        #pragma unroll
        for (int i = tid; i < TF2v / 4; i += 256) {
            s_d[i] = d2p[i];
            s_f[i] = f0p[i];
        }
    }
    __syncthreads();

    const float4* __restrict__ base =
        (const float4*)attn + ((size_t)(b * TPv + rg * RPB)) * (TF2v / 4);

    for (int rp = 0; rp < RPB; rp += 2) {
        const float4* __restrict__ row0 = base + (size_t)rp * (TF2v / 4);
        const float4* __restrict__ row1 = row0 + (TF2v / 4);
        float sa0 = 0.f, sc0 = 0.f, sm0 = 0.f;
        float sa1 = 0.f, sc1 = 0.f, sm1 = 0.f;
        #pragma unroll
        for (int k = 0; k < 4; ++k) {
            int idx = tid + 256 * k;
            float4 a0 = __ldcs(&row0[idx]);
            float4 a1 = __ldcs(&row1[idx]);
            float4 d  = s_d[idx];
            float4 f  = s_f[idx];
            sa0 += (a0.x + a0.y) + (a0.z + a0.w);
            sc0 += a0.x * d.x + a0.y * d.y + a0.z * d.z + a0.w * d.w;
            sm0 += a0.x * f.x + a0.y * f.y + a0.z * f.z + a0.w * f.w;
            sa1 += (a1.x + a1.y) + (a1.z + a1.w);
            sc1 += a1.x * d.x + a1.y * d.y + a1.z * d.z + a1.w * d.w;
            sm1 += a1.x * f.x + a1.y * f.y + a1.z * f.z + a1.w * f.w;
        }
        #pragma unroll
        for (int o = 16; o > 0; o >>= 1) {
            sa0 += __shfl_down_sync(0xffffffffu, sa0, o);
            sc0 += __shfl_down_sync(0xffffffffu, sc0, o);
            sm0 += __shfl_down_sync(0xffffffffu, sm0, o);
            sa1 += __shfl_down_sync(0xffffffffu, sa1, o);
            sc1 += __shfl_down_sync(0xffffffffu, sc1, o);
            sm1 += __shfl_down_sync(0xffffffffu, sm1, o);
        }
        if (l == 0) {
            red[rp][0][w]     = sa0; red[rp][1][w]     = sc0; red[rp][2][w]     = sm0;
            red[rp + 1][0][w] = sa1; red[rp + 1][1][w] = sc1; red[rp + 1][2][w] = sm1;
        }
    }
    __syncthreads();

    if (tid < RPB) {
        float sa = 0.0f, sc = 0.0f, sm = 0.0f;
        #pragma unroll
        for (int i = 0; i < 8; ++i) {
            sa += red[tid][0][i]; sc += red[tid][1][i]; sm += red[tid][2][i];
        }
        float denom = fmaxf(2.0f * sa, 1.0f);
        float inv   = 1.0f / (denom + EPSv);
        int bid = b * TPv + rg * RPB + tid;
        out[bid]            = sc * inv;   // curv_phn
        out[Bv * TPv + bid] = sm * inv;   // mean_phn
    }

    // ---- last-block epilogue ----
    __threadfence();
    __syncthreads();
    if (tid == 0) {
        unsigned old = atomicAdd(&g_ctr, 1u);
        s_last = (old == (unsigned)(gridDim.x - 1)) ? 1 : 0;
    }
    __syncthreads();
    if (!s_last) return;
    if (tid == 0) g_ctr = 0;
    __threadfence();

    const float OODM =  21.688259064691245f;   // 12*log2(350/100)
    const float OODC = -71.589411415945055f;   // 12*log2(1.6/100)

    #pragma unroll
    for (int pass = 0; pass < 2; ++pass) {
        int bb = w + 8 * pass;
        float dm = 0.0f, vm = 0.0f, dc = 0.0f, vc = 0.0f;
        #pragma unroll
        for (int k = 0; k < TPv / 32; ++k) {
            int p = l + 32 * k;
            float u  = uv[bb * TPv + p];
            float cv = out[bb * TPv + p];
            float mv = out[Bv * TPv + bb * TPv + p];

            float pvm = mv * u;
            float vmi = (pvm != 0.0f) ? 1.0f : 0.0f;
            float semim = 12.0f * log2f(fmaxf(pvm, 1e-6f) * 0.01f);
            dm += fmaxf(OODM - semim, 0.0f) * vmi;
            vm += vmi;

            float pvc = cv * u;
            float vci = (pvc != 0.0f) ? 1.0f : 0.0f;
            float semic = 12.0f * log2f(fmaxf(pvc, 1e-6f) * 0.01f);
            dc += fmaxf(OODC - semic, 0.0f) * vci;
            vc += vci;
        }
        #pragma unroll
        for (int o = 16; o > 0; o >>= 1) {
            dm += __shfl_down_sync(0xffffffffu, dm, o);
            vm += __shfl_down_sync(0xffffffffu, vm, o);
            dc += __shfl_down_sync(0xffffffffu, dc, o);
            vc += __shfl_down_sync(0xffffffffu, vc, o);
        }
        if (l == 0) s_e[bb] = dm / fmaxf(vm, 1.0f) + dc / fmaxf(vc, 1.0f);
    }
    __syncthreads();

    if (tid == 0) {
        float e[Bv];
        float m = 0.0f;
        #pragma unroll
        for (int i = 0; i < Bv; ++i) { e[i] = s_e[i]; m += e[i]; }
        m /= (float)Bv;
        float var = 0.0f;
        #pragma unroll
        for (int i = 0; i < Bv; ++i) { float dd = e[i] - m; var += dd * dd; }
        var /= (float)Bv;
        float sd = fmaxf(sqrtf(var), 1e-6f);
        float x[Bv], mx = -1e30f;
        #pragma unroll
        for (int i = 0; i < Bv; ++i) { x[i] = -(e[i] - m) / sd; mx = fmaxf(mx, x[i]); }
        float s = 0.0f;
        #pragma unroll
        for (int i = 0; i < Bv; ++i) { x[i] = expf(x[i] - mx); s += x[i]; }
        float s2 = 0.0f;
        #pragma unroll
        for (int i = 0; i < Bv; ++i) { float wv = x[i] / s; x[i] = wv; s2 += wv * wv; }
        #pragma unroll
        for (int i = 0; i < Bv; ++i) out[2 * Bv * TPv + i] = (float)Bv * x[i];
        out[2 * Bv * TPv + Bv] = 1.0f / s2;
    }
}

// ---------------------------------------------------------------------------

extern "C" void kernel_launch(void* const* d_in, const int* in_sizes, int n_in,
                              void* d_out, int out_size) {
    const float* f0   = (const float*)d_in[0];   // [B, TF]
    const float* attn = (const float*)d_in[1];   // [B, TP, TF2]
    const float* uv   = (const float*)d_in[2];   // [B, TP]
    float* out = (float*)d_out;                  // curv | mean | B*wts | ess

    frame_kernel<<<Bv * 32, 256>>>(f0);
    row_kernel<<<(Bv * TPv) / RPB, 256>>>(attn, uv, out);
}